// round 14
// baseline (speedup 1.0000x reference)
#include <cuda_runtime.h>
#include <cuda_bf16.h>
#include <cstdint>

#define THREADS 256
#define NCOLS   8192
#define FVECS   8            // float4 chunks per thread: 8*4*256 = 8192
#define KTOP    64
#define RPT     2            // rows per ticket (64 KB continuous stream)
#define CAPR    512          // candidates per row (expected ~186, 24 sigma)
#define MCAPR   512          // marked vec4s per row (expected ~170)
#define TBCAP   128          // in-bin buffer for final exact rank
#define PIVOT   2.0f
#define GRID    888          // 148 SMs x 6 CTAs

// Monotone ticket counter; each launch consumes exactly rows_t + GRID tickets
// (rows_t work tickets + one stop ticket per CTA), so the mapping
// ticket -> row base is launch-invariant (graph-replay safe, no reset kernel).
__device__ unsigned long long g_ticket;

__device__ __forceinline__ unsigned mono(unsigned u) {
    return u ^ ((unsigned)((int)u >> 31) | 0x80000000u);
}

__device__ __forceinline__ void stcs4(float4* p, float4 v) {
    asm volatile("st.global.cs.v4.f32 [%0], {%1,%2,%3,%4};"
                 :: "l"(p), "f"(v.x), "f"(v.y), "f"(v.z), "f"(v.w));
}

__global__ __launch_bounds__(THREADS, 6)
void topk_mask_kernel(const float* __restrict__ x, float* __restrict__ out,
                      int rows) {
    const int tid  = threadIdx.x;
    const int lane = tid & 31;
    const int wid  = tid >> 5;
    const unsigned rows_t = ((unsigned)rows + RPT - 1) / RPT;
    const unsigned long long EPOCH = (unsigned long long)rows_t + GRID;

    __shared__ unsigned hist[256];
    __shared__ unsigned wsum[8];
    __shared__ unsigned long long sh_t;
    __shared__ unsigned sh_m[RPT], sh_c[RPT];
    __shared__ unsigned sh_B, sh_kB, sh_tc;
    __shared__ unsigned long long sh_T;
    __shared__ unsigned long long cand[RPT * CAPR];          // 8 KB
    __shared__ __align__(8) unsigned marks[RPT * MCAPR];     // 4 KB; tb/tcol reuse
    __shared__ unsigned sh_prefix, sh_kk, sh_tcnt, sh_cut;   // fallback state
    unsigned long long* tb = reinterpret_cast<unsigned long long*>(marks);

    if (tid == 0) {
        sh_m[0] = sh_m[1] = 0u; sh_c[0] = sh_c[1] = 0u; sh_tc = 0u;
        sh_t = atomicAdd(&g_ticket, 1ull);
    }
    __syncthreads();
    unsigned long long t = sh_t;

    while (true) {
        const unsigned base = (unsigned)(t % EPOCH) * RPT;
        if (base >= (unsigned)rows) break;

        // ---- Phase 1: stream RPT rows continuously (zeros out, mark vec4s) --
        const float4 z = make_float4(0.f, 0.f, 0.f, 0.f);
        #pragma unroll
        for (int h = 0; h < RPT; ++h) {
            const unsigned rowh = base + (unsigned)h;
            if (rowh >= (unsigned)rows) break;    // CTA-uniform
            const float4* __restrict__ in4 =
                reinterpret_cast<const float4*>(x + (size_t)rowh * NCOLS);
            float4* __restrict__ out4 =
                reinterpret_cast<float4*>(out + (size_t)rowh * NCOLS);
            #pragma unroll
            for (int jj = 0; jj < FVECS; ++jj) {
                const int idx = tid + THREADS * jj;
                const float4 v = in4[idx];
                stcs4(&out4[idx], z);
                const float m = fmaxf(fmaxf(v.x, v.y), fmaxf(v.z, v.w));
                if (m > PIVOT) {
                    const unsigned pos = atomicAdd(&sh_m[h], 1u);
                    if (pos < MCAPR) marks[h * MCAPR + pos] = (unsigned)idx;
                }
            }
        }
        __syncthreads();
        if (tid == 0) sh_t = atomicAdd(&g_ticket, 1ull);   // grab next early
        if (tid < 128) hist[tid] = 0u;                     // for h=0 select
        if (tid == 129) sh_tc = 0u;

        // ---- Phase 2: rescan marked vec4s (L1 hits) -> exact candidates ----
        #pragma unroll
        for (int h = 0; h < RPT; ++h) {
            const unsigned rowh = base + (unsigned)h;
            if (rowh >= (unsigned)rows) break;
            const unsigned mh = sh_m[h];
            if (mh > MCAPR) continue;             // fallback will handle
            const float4* __restrict__ in4 =
                reinterpret_cast<const float4*>(x + (size_t)rowh * NCOLS);
            for (unsigned s = tid; s < mh; s += THREADS) {
                const unsigned idx = marks[h * MCAPR + s];
                const float4 v = in4[idx];
                #pragma unroll
                for (int c = 0; c < 4; ++c) {
                    const float f = (&v.x)[c];
                    if (f > PIVOT) {
                        const unsigned pos = atomicAdd(&sh_c[h], 1u);
                        if (pos < CAPR)
                            cand[h * CAPR + pos] =
                                ((unsigned long long)__float_as_uint(f) << 13) |
                                (unsigned long long)(8191u - (4u * idx + (unsigned)c));
                    }
                }
            }
        }
        __syncthreads();
        const unsigned long long nt = sh_t;

        // ---- Prefetch next ticket's rows into L2 (32 KB per row) ----
        {
            const unsigned nb = (unsigned)(nt % EPOCH) * RPT;
            #pragma unroll
            for (int h = 0; h < RPT; ++h) {
                if (nb + h < (unsigned)rows) {
                    const char* p = reinterpret_cast<const char*>(
                        x + (size_t)(nb + h) * NCOLS) + (size_t)tid * 128;
                    asm volatile("prefetch.global.L2 [%0];" :: "l"(p));
                }
            }
        }

        // ================= Per-row select + scatter =================
        for (int h = 0; h < RPT; ++h) {
            const unsigned rowh = base + (unsigned)h;
            if (rowh >= (unsigned)rows) break;    // CTA-uniform
            const unsigned mcnt = sh_m[h];
            const unsigned cnt  = sh_c[h];
            const unsigned long long* ch = cand + h * CAPR;
            float* __restrict__ orow = out + (size_t)rowh * NCOLS;

            bool done = false;
            if (mcnt <= MCAPR && cnt >= KTOP && cnt <= CAPR) {
                // ---- 128-bin monotone histogram over candidate bits ----
                // (hist + sh_tc cleared: pre-loop for h=0, end of h-1 after)
                for (unsigned s = tid; s < cnt; s += THREADS) {
                    const unsigned bits = (unsigned)(ch[s] >> 13);
                    unsigned d = (bits - 0x40000000u) >> 17;
                    if (d > 127u) d = 127u;
                    atomicAdd(&hist[d], 1u);
                }
                __syncthreads();

                unsigned v = 0u, sc = 0u;
                if (tid < 128) {
                    v = hist[127 - tid];
                    sc = v;
                    #pragma unroll
                    for (int off = 1; off < 32; off <<= 1) {
                        const unsigned y = __shfl_up_sync(0xffffffffu, sc, off);
                        if (lane >= off) sc += y;
                    }
                    if (lane == 31) wsum[wid] = sc;
                }
                __syncthreads();
                if (tid < 128) {
                    unsigned add = 0u;
                    #pragma unroll
                    for (int w = 0; w < 4; ++w) add += (w < wid) ? wsum[w] : 0u;
                    const unsigned incl = sc + add;
                    const unsigned excl = incl - v;
                    if (excl < KTOP && KTOP <= incl) {
                        sh_B  = 127u - (unsigned)tid;
                        sh_kB = KTOP - excl;
                    }
                }
                __syncthreads();
                const unsigned B  = sh_B;
                const unsigned kB = sh_kB;

                // ---- collect in-bin candidates (expected 2-5) ----
                for (unsigned s = tid; s < cnt; s += THREADS) {
                    const unsigned long long cv = ch[s];
                    const unsigned bits = (unsigned)(cv >> 13);
                    unsigned d = (bits - 0x40000000u) >> 17;
                    if (d > 127u) d = 127u;
                    if (d == B) {
                        const unsigned p2 = atomicAdd(&sh_tc, 1u);
                        if (p2 < TBCAP) tb[p2] = cv;
                    }
                }
                __syncthreads();
                const unsigned tc = sh_tc;

                if (tc <= TBCAP) {
                    for (unsigned s = tid; s < tc; s += THREADS) {
                        const unsigned long long vv = tb[s];
                        unsigned rr = 0u;
                        for (unsigned j = 0; j < tc; ++j)
                            rr += (tb[j] > vv) ? 1u : 0u;
                        if (rr == kB - 1u) sh_T = vv;
                    }
                    __syncthreads();
                    const unsigned long long T = sh_T;
                    // clear for next row's select (ordered by end barrier)
                    if (tid < 128) hist[tid] = 0u;
                    if (tid == 129) sh_tc = 0u;

                    // ---- scatter the 64 kept values over the zeros ----
                    for (unsigned s = tid; s < cnt; s += THREADS) {
                        const unsigned long long cv = ch[s];
                        const unsigned bits = (unsigned)(cv >> 13);
                        unsigned d = (bits - 0x40000000u) >> 17;
                        if (d > 127u) d = 127u;
                        if (d > B || (d == B && cv >= T)) {
                            const unsigned col = 8191u - (unsigned)(cv & 8191ull);
                            orow[col] = __uint_as_float(bits);
                        }
                    }
                    __syncthreads();   // clears visible; tb free for next row
                    done = true;
                }
            }

            if (!done) {
                // ========= Generic fallback (never taken for N(0,1)) =========
                const float4* __restrict__ in4 =
                    reinterpret_cast<const float4*>(x + (size_t)rowh * NCOLS);
                __syncthreads();
                if (tid == 0) { sh_prefix = 0u; sh_kk = KTOP; }

                for (int p = 0; p < 4; ++p) {
                    __syncthreads();
                    const unsigned prefix = sh_prefix;
                    const unsigned kRem   = sh_kk;
                    hist[tid] = 0u;
                    __syncthreads();
                    for (int jj = 0; jj < FVECS; ++jj) {
                        const float4 v = in4[tid + THREADS * jj];
                        #pragma unroll
                        for (int c = 0; c < 4; ++c) {
                            const unsigned key = mono(__float_as_uint((&v.x)[c]));
                            const bool act = (p == 0) ||
                                             ((key >> (32 - 8 * p)) == prefix);
                            if (act)
                                atomicAdd(&hist[(key >> (24 - 8 * p)) & 0xffu], 1u);
                        }
                    }
                    __syncthreads();
                    const unsigned v  = hist[255 - tid];
                    unsigned sc = v;
                    #pragma unroll
                    for (int off = 1; off < 32; off <<= 1) {
                        const unsigned y = __shfl_up_sync(0xffffffffu, sc, off);
                        if (lane >= off) sc += y;
                    }
                    if (lane == 31) wsum[wid] = sc;
                    __syncthreads();
                    unsigned add = 0u;
                    #pragma unroll
                    for (int w = 0; w < 8; ++w) add += (w < wid) ? wsum[w] : 0u;
                    const unsigned incl = sc + add;
                    const unsigned excl = incl - v;
                    if (excl < kRem && kRem <= incl) {
                        sh_prefix = (prefix << 8) | (255u - (unsigned)tid);
                        sh_kk     = kRem - excl;
                    }
                }
                __syncthreads();
                const unsigned Tk = sh_prefix;
                const unsigned kT = sh_kk;

                unsigned* tcol = marks;            // dead by now; cap RPT*MCAPR
                if (tid == 0) sh_tcnt = 0u;
                __syncthreads();
                for (int jj = 0; jj < FVECS; ++jj) {
                    const float4 v = in4[tid + THREADS * jj];
                    #pragma unroll
                    for (int c = 0; c < 4; ++c) {
                        const unsigned key = mono(__float_as_uint((&v.x)[c]));
                        if (key == Tk) {
                            const unsigned col =
                                4u * ((unsigned)tid + THREADS * jj) + (unsigned)c;
                            const unsigned pos = atomicAdd(&sh_tcnt, 1u);
                            if (pos < RPT * MCAPR) tcol[pos] = col;
                        }
                    }
                }
                __syncthreads();
                if (tid == 0) {
                    unsigned c = sh_tcnt;
                    if (c > RPT * MCAPR) c = RPT * MCAPR;
                    unsigned cut = 0xffffffffu;
                    for (unsigned s = 0; s < kT; ++s) {
                        unsigned mn = 0xffffffffu, mi = 0u;
                        for (unsigned i = 0; i < c; ++i)
                            if (tcol[i] < mn) { mn = tcol[i]; mi = i; }
                        tcol[mi] = 0xffffffffu;
                        cut = mn;
                    }
                    sh_cut = cut;
                }
                __syncthreads();
                const unsigned cut = sh_cut;

                float4* __restrict__ o4 =
                    reinterpret_cast<float4*>(out + (size_t)rowh * NCOLS);
                for (int jj = 0; jj < FVECS; ++jj) {
                    const float4 v = in4[tid + THREADS * jj];
                    float4 o;
                    #pragma unroll
                    for (int c = 0; c < 4; ++c) {
                        const unsigned key = mono(__float_as_uint((&v.x)[c]));
                        const unsigned col =
                            4u * ((unsigned)tid + THREADS * jj) + (unsigned)c;
                        const bool keep = (key > Tk) || (key == Tk && col <= cut);
                        (&o.x)[c] = keep ? (&v.x)[c] : 0.0f;
                    }
                    o4[tid + THREADS * jj] = o;
                }
                // restore select-state invariants for the next row
                hist[tid] = 0u;
                if (tid == 0) sh_tc = 0u;
                __syncthreads();
            }
        }

        // ---- reset per-row counters for the next ticket ----
        if (tid == 0) { sh_m[0] = sh_m[1] = 0u; sh_c[0] = sh_c[1] = 0u; }
        __syncthreads();
        t = nt;
    }
}

extern "C" void kernel_launch(void* const* d_in, const int* in_sizes, int n_in,
                              void* d_out, int out_size) {
    const float* x = (const float*)d_in[0];
    float* out = (float*)d_out;
    const int rows = in_sizes[0] / NCOLS;
    topk_mask_kernel<<<GRID, THREADS>>>(x, out, rows);
}

// round 15
// speedup vs baseline: 1.2103x; 1.2103x over previous
#include <cuda_runtime.h>
#include <cuda_bf16.h>
#include <cstdint>

#define THREADS 256
#define NCOLS   8192
#define FVECS   8            // float4 chunks per thread: 8*4*256 = 8192
#define KTOP    64
#define CAP     1024         // candidate buffer (expected ~186)
#define MCAP    768          // marked-vec4 buffer (expected ~170)
#define TBCAP   128          // in-bin buffer for final exact rank
#define PIVOT   2.0f
#define GRID    888          // 148 SMs x 6 CTAs

// Monotone ticket counter; each launch consumes exactly rows + GRID tickets,
// so row = ticket % (rows + GRID) is launch-invariant (graph-replay safe).
__device__ unsigned long long g_ticket;

__device__ __forceinline__ unsigned mono(unsigned u) {
    return u ^ ((unsigned)((int)u >> 31) | 0x80000000u);
}

__device__ __forceinline__ void stcs4(float4* p, float4 v) {
    asm volatile("st.global.cs.v4.f32 [%0], {%1,%2,%3,%4};"
                 :: "l"(p), "f"(v.x), "f"(v.y), "f"(v.z), "f"(v.w));
}

__global__ __launch_bounds__(THREADS, 6)
void topk_mask_kernel(const float* __restrict__ x, float* __restrict__ out,
                      int rows) {
    const int tid  = threadIdx.x;
    const int lane = tid & 31;
    const int wid  = tid >> 5;
    const unsigned long long EPOCH = (unsigned long long)rows + GRID;

    __shared__ unsigned hist[256];
    __shared__ unsigned wsum[8];
    __shared__ unsigned long long sh_t;
    __shared__ unsigned sh_cnt, sh_mcnt, sh_B, sh_kB, sh_tc;
    __shared__ unsigned long long sh_T;
    __shared__ unsigned long long cand[CAP];
    __shared__ unsigned long long mbuf[MCAP / 2];   // marks(u32)/tb(u64) reuse
    unsigned* marks = reinterpret_cast<unsigned*>(mbuf);

    if (tid == 0) {
        sh_cnt = 0u; sh_mcnt = 0u; sh_tc = 0u;
        sh_t = atomicAdd(&g_ticket, 1ull);
    }
    __syncthreads();
    unsigned long long t = sh_t;

    while (true) {
        const unsigned r = (unsigned)(t % EPOCH);
        if (r >= (unsigned)rows) break;

        const float4* __restrict__ in4 =
            reinterpret_cast<const float4*>(x + (size_t)r * NCOLS);
        float4* __restrict__ out4 =
            reinterpret_cast<float4*>(out + (size_t)r * NCOLS);
        float* __restrict__ orow = out + (size_t)r * NCOLS;

        // ---- Phase 1: fused pass: stream zeros out, mark vec4s with f>PIVOT --
        const float4 z = make_float4(0.f, 0.f, 0.f, 0.f);
        #pragma unroll
        for (int jj = 0; jj < FVECS; ++jj) {
            const int idx = tid + THREADS * jj;
            const float4 v = in4[idx];
            stcs4(&out4[idx], z);
            const float m = fmaxf(fmaxf(v.x, v.y), fmaxf(v.z, v.w));
            if (m > PIVOT) {
                const unsigned pos = atomicAdd(&sh_mcnt, 1u);
                if (pos < MCAP) marks[pos] = (unsigned)idx;
            }
        }
        __syncthreads();
        const unsigned mcnt = sh_mcnt;
        if (tid == 0) sh_t = atomicAdd(&g_ticket, 1ull);   // grab next early
        if (tid < 128) hist[tid] = 0u;                     // clear fast bins

        // ---- Phase 2: rescan marked vec4s (L1 hits), exact candidates ----
        if (mcnt <= MCAP) {
            for (unsigned s = tid; s < mcnt; s += THREADS) {
                const unsigned idx = marks[s];
                const float4 v = in4[idx];
                #pragma unroll
                for (int c = 0; c < 4; ++c) {
                    const float f = (&v.x)[c];
                    if (f > PIVOT) {
                        const unsigned pos = atomicAdd(&sh_cnt, 1u);
                        if (pos < CAP)
                            cand[pos] =
                                ((unsigned long long)__float_as_uint(f) << 13) |
                                (unsigned long long)(8191u - (4u * idx + (unsigned)c));
                    }
                }
            }
        }
        __syncthreads();
        const unsigned cnt = sh_cnt;
        const unsigned long long nt = sh_t;

        // ---- Prefetch next row into L2 (1 x 128B line/thread = 32 KB) ----
        {
            const unsigned nr = (unsigned)(nt % EPOCH);
            if (nr < (unsigned)rows) {
                const char* p =
                    reinterpret_cast<const char*>(x + (size_t)nr * NCOLS)
                    + (size_t)tid * 128;
                asm volatile("prefetch.global.L2 [%0];" :: "l"(p));
            }
        }

        bool done = false;
        if (mcnt <= MCAP && cnt >= KTOP && cnt <= CAP) {
            // ---- Phase 3: 128-bin monotone histogram over candidate bits ----
            for (unsigned s = tid; s < cnt; s += THREADS) {
                const unsigned bits = (unsigned)(cand[s] >> 13);
                unsigned d = (bits - 0x40000000u) >> 17;
                if (d > 127u) d = 127u;
                atomicAdd(&hist[d], 1u);
            }
            __syncthreads();

            unsigned v = 0u, sc = 0u;
            if (tid < 128) {
                v = hist[127 - tid];
                sc = v;
                #pragma unroll
                for (int off = 1; off < 32; off <<= 1) {
                    const unsigned y = __shfl_up_sync(0xffffffffu, sc, off);
                    if (lane >= off) sc += y;
                }
                if (lane == 31) wsum[wid] = sc;
            }
            __syncthreads();
            if (tid < 128) {
                unsigned add = 0u;
                #pragma unroll
                for (int w = 0; w < 4; ++w) add += (w < wid) ? wsum[w] : 0u;
                const unsigned incl = sc + add;
                const unsigned excl = incl - v;
                if (excl < KTOP && KTOP <= incl) {
                    sh_B  = 127u - (unsigned)tid;
                    sh_kB = KTOP - excl;
                }
            }
            __syncthreads();
            const unsigned B  = sh_B;
            const unsigned kB = sh_kB;

            // ---- Phase 4: collect in-bin candidates (expected 2-5) ----
            unsigned long long* tb = mbuf;
            for (unsigned s = tid; s < cnt; s += THREADS) {
                const unsigned long long cv = cand[s];
                const unsigned bits = (unsigned)(cv >> 13);
                unsigned d = (bits - 0x40000000u) >> 17;
                if (d > 127u) d = 127u;
                if (d == B) {
                    const unsigned p2 = atomicAdd(&sh_tc, 1u);
                    if (p2 < TBCAP) tb[p2] = cv;
                }
            }
            __syncthreads();
            const unsigned tc = sh_tc;

            if (tc <= TBCAP) {
                for (unsigned s = tid; s < tc; s += THREADS) {
                    const unsigned long long vv = tb[s];
                    unsigned rr = 0u;
                    for (unsigned j = 0; j < tc; ++j)
                        rr += (tb[j] > vv) ? 1u : 0u;
                    if (rr == kB - 1u) sh_T = vv;
                }
                __syncthreads();
                const unsigned long long T = sh_T;
                if (tid == 0) { sh_cnt = 0u; sh_mcnt = 0u; sh_tc = 0u; }

                // ---- Phase 5: scatter the 64 kept values over the zeros ----
                for (unsigned s = tid; s < cnt; s += THREADS) {
                    const unsigned long long cv = cand[s];
                    const unsigned bits = (unsigned)(cv >> 13);
                    unsigned d = (bits - 0x40000000u) >> 17;
                    if (d > 127u) d = 127u;
                    if (d > B || (d == B && cv >= T)) {
                        const unsigned col = 8191u - (unsigned)(cv & 8191ull);
                        orow[col] = __uint_as_float(bits);
                    }
                }
                done = true;
            }
        }

        if (!done) {
            // ============ Generic fallback (never taken for N(0,1)) ==========
            __shared__ unsigned sh_prefix, sh_kk, sh_tcnt, sh_cut;
            __syncthreads();
            if (tid == 0) { sh_prefix = 0u; sh_kk = KTOP; }

            for (int p = 0; p < 4; ++p) {
                __syncthreads();
                const unsigned prefix = sh_prefix;
                const unsigned kRem   = sh_kk;
                hist[tid] = 0u;
                __syncthreads();
                for (int jj = 0; jj < FVECS; ++jj) {
                    const float4 v = in4[tid + THREADS * jj];
                    #pragma unroll
                    for (int c = 0; c < 4; ++c) {
                        const unsigned key = mono(__float_as_uint((&v.x)[c]));
                        const bool act = (p == 0) ||
                                         ((key >> (32 - 8 * p)) == prefix);
                        if (act)
                            atomicAdd(&hist[(key >> (24 - 8 * p)) & 0xffu], 1u);
                    }
                }
                __syncthreads();
                const unsigned v  = hist[255 - tid];
                unsigned sc = v;
                #pragma unroll
                for (int off = 1; off < 32; off <<= 1) {
                    const unsigned y = __shfl_up_sync(0xffffffffu, sc, off);
                    if (lane >= off) sc += y;
                }
                if (lane == 31) wsum[wid] = sc;
                __syncthreads();
                unsigned add = 0u;
                #pragma unroll
                for (int w = 0; w < 8; ++w) add += (w < wid) ? wsum[w] : 0u;
                const unsigned incl = sc + add;
                const unsigned excl = incl - v;
                if (excl < kRem && kRem <= incl) {
                    sh_prefix = (prefix << 8) | (255u - (unsigned)tid);
                    sh_kk     = kRem - excl;
                }
            }
            __syncthreads();
            const unsigned Tk = sh_prefix;
            const unsigned kT = sh_kk;

            unsigned* tcol = (unsigned*)cand;
            if (tid == 0) sh_tcnt = 0u;
            __syncthreads();
            for (int jj = 0; jj < FVECS; ++jj) {
                const float4 v = in4[tid + THREADS * jj];
                #pragma unroll
                for (int c = 0; c < 4; ++c) {
                    const unsigned key = mono(__float_as_uint((&v.x)[c]));
                    if (key == Tk) {
                        const unsigned col =
                            4u * ((unsigned)tid + THREADS * jj) + (unsigned)c;
                        const unsigned pos = atomicAdd(&sh_tcnt, 1u);
                        if (pos < 2u * CAP) tcol[pos] = col;
                    }
                }
            }
            __syncthreads();
            if (tid == 0) {
                unsigned c = sh_tcnt; if (c > 2u * CAP) c = 2u * CAP;
                unsigned cut = 0xffffffffu;
                for (unsigned s = 0; s < kT; ++s) {
                    unsigned mn = 0xffffffffu, mi = 0u;
                    for (unsigned i = 0; i < c; ++i)
                        if (tcol[i] < mn) { mn = tcol[i]; mi = i; }
                    tcol[mi] = 0xffffffffu;
                    cut = mn;
                }
                sh_cut = cut;
            }
            __syncthreads();
            const unsigned cut = sh_cut;

            for (int jj = 0; jj < FVECS; ++jj) {
                const float4 v = in4[tid + THREADS * jj];
                float4 o;
                #pragma unroll
                for (int c = 0; c < 4; ++c) {
                    const unsigned key = mono(__float_as_uint((&v.x)[c]));
                    const unsigned col =
                        4u * ((unsigned)tid + THREADS * jj) + (unsigned)c;
                    const bool keep = (key > Tk) || (key == Tk && col <= cut);
                    (&o.x)[c] = keep ? (&v.x)[c] : 0.0f;
                }
                out4[tid + THREADS * jj] = o;
            }
            __syncthreads();
            if (tid == 0) { sh_cnt = 0u; sh_mcnt = 0u; sh_tc = 0u; }
        }

        __syncthreads();   // counter resets visible before next row's pushes
        t = nt;
    }
}

extern "C" void kernel_launch(void* const* d_in, const int* in_sizes, int n_in,
                              void* d_out, int out_size) {
    const float* x = (const float*)d_in[0];
    float* out = (float*)d_out;
    const int rows = in_sizes[0] / NCOLS;
    topk_mask_kernel<<<GRID, THREADS>>>(x, out, rows);
}

// round 16
// speedup vs baseline: 1.2183x; 1.0067x over previous
#include <cuda_runtime.h>
#include <cuda_bf16.h>
#include <cstdint>

#define THREADS 256
#define NCOLS   8192
#define FVECS   8            // float4 chunks per thread: 8*4*256 = 8192
#define KTOP    64
#define CAP     1024         // candidate buffer (expected ~186)
#define MCAP    768          // marked-vec4 buffer (expected ~170)
#define TBCAP   128          // in-bin buffer for final exact rank
#define PIVOT   2.0f
#define WAVE    888          // resident wave: 148 SMs x 6 CTAs

__device__ __forceinline__ unsigned mono(unsigned u) {
    return u ^ ((unsigned)((int)u >> 31) | 0x80000000u);
}

__global__ __launch_bounds__(THREADS, 6)
void topk_mask_kernel(const float* __restrict__ x, float* __restrict__ out,
                      int rows) {
    const int row  = blockIdx.x;
    const int tid  = threadIdx.x;
    const int lane = tid & 31;
    const int wid  = tid >> 5;

    const float4* __restrict__ in4 =
        reinterpret_cast<const float4*>(x + (size_t)row * NCOLS);
    float4* __restrict__ out4 =
        reinterpret_cast<float4*>(out + (size_t)row * NCOLS);
    float* __restrict__ orow = out + (size_t)row * NCOLS;

    __shared__ unsigned hist[256];
    __shared__ unsigned wsum[8];
    __shared__ unsigned sh_cnt, sh_mcnt, sh_B, sh_kB, sh_tc;
    __shared__ unsigned long long sh_T;
    __shared__ unsigned long long cand[CAP];
    __shared__ unsigned long long mbuf[MCAP / 2];   // marks(u32)/tb(u64) reuse
    unsigned* marks = reinterpret_cast<unsigned*>(mbuf);

    if (tid == 0) { sh_cnt = 0u; sh_mcnt = 0u; sh_tc = 0u; }
    __syncthreads();

    // ---- Phase 1: single fused pass: zero output, mark vec4s with any f>2 ----
    const float4 z = make_float4(0.f, 0.f, 0.f, 0.f);
    #pragma unroll
    for (int jj = 0; jj < FVECS; ++jj) {
        const int idx = tid + THREADS * jj;
        const float4 v = in4[idx];
        out4[idx] = z;
        const float m = fmaxf(fmaxf(v.x, v.y), fmaxf(v.z, v.w));
        if (m > PIVOT) {
            const unsigned pos = atomicAdd(&sh_mcnt, 1u);
            if (pos < MCAP) marks[pos] = (unsigned)idx;
        }
    }
    __syncthreads();
    const unsigned mcnt = sh_mcnt;

    // ---- Phase 2: rescan marked vec4s (L1/L2 hits), extract exact candidates ----
    if (mcnt <= MCAP) {
        for (unsigned s = tid; s < mcnt; s += THREADS) {
            const unsigned idx = marks[s];
            const float4 v = in4[idx];
            #pragma unroll
            for (int c = 0; c < 4; ++c) {
                const float f = (&v.x)[c];
                if (f > PIVOT) {
                    const unsigned pos = atomicAdd(&sh_cnt, 1u);
                    if (pos < CAP)
                        cand[pos] =
                            ((unsigned long long)__float_as_uint(f) << 13) |
                            (unsigned long long)(8191u - (4u * idx + (unsigned)c));
                }
            }
        }
    }
    __syncthreads();
    const unsigned cnt = sh_cnt;

    // ---- Prefetch the row one wave ahead into L2 (32 KB; covers the CTA
    //      that will occupy this SM slot next wave) ----
    {
        const int nr = row + WAVE;
        if (nr < rows) {
            const char* p = reinterpret_cast<const char*>(x + (size_t)nr * NCOLS)
                            + (size_t)tid * 128;
            asm volatile("prefetch.global.L2 [%0];" :: "l"(p));
        }
    }

    if (mcnt <= MCAP && cnt >= KTOP && cnt <= CAP) {
        // ---- Phase 3: 128-bin monotone histogram over candidate bits ----
        hist[tid] = 0u;
        __syncthreads();
        for (unsigned s = tid; s < cnt; s += THREADS) {
            const unsigned bits = (unsigned)(cand[s] >> 13);
            unsigned d = (bits - 0x40000000u) >> 17;
            if (d > 127u) d = 127u;
            atomicAdd(&hist[d], 1u);
        }
        __syncthreads();

        // suffix-scan from top bin (threads 0..127 handle bin 127-tid)
        unsigned v = 0u, sc = 0u;
        if (tid < 128) {
            v = hist[127 - tid];
            sc = v;
            #pragma unroll
            for (int off = 1; off < 32; off <<= 1) {
                const unsigned y = __shfl_up_sync(0xffffffffu, sc, off);
                if (lane >= off) sc += y;
            }
            if (lane == 31) wsum[wid] = sc;
        }
        __syncthreads();
        if (tid < 128) {
            unsigned add = 0u;
            #pragma unroll
            for (int w = 0; w < 4; ++w) add += (w < wid) ? wsum[w] : 0u;
            const unsigned incl = sc + add;
            const unsigned excl = incl - v;
            if (excl < KTOP && KTOP <= incl) {
                sh_B  = 127u - (unsigned)tid;
                sh_kB = KTOP - excl;
            }
        }
        __syncthreads();
        const unsigned B  = sh_B;
        const unsigned kB = sh_kB;

        // ---- Phase 4: collect in-bin candidates (expected 2-5) ----
        unsigned long long* tb = mbuf;   // marks no longer needed
        for (unsigned s = tid; s < cnt; s += THREADS) {
            const unsigned long long cv = cand[s];
            const unsigned bits = (unsigned)(cv >> 13);
            unsigned d = (bits - 0x40000000u) >> 17;
            if (d > 127u) d = 127u;
            if (d == B) {
                const unsigned p = atomicAdd(&sh_tc, 1u);
                if (p < TBCAP) tb[p] = cv;
            }
        }
        __syncthreads();
        const unsigned tc = sh_tc;

        if (tc <= TBCAP) {
            // exact rank among the few in-bin candidates (unique packed keys)
            for (unsigned s = tid; s < tc; s += THREADS) {
                const unsigned long long vv = tb[s];
                unsigned r = 0u;
                for (unsigned j = 0; j < tc; ++j)
                    r += (tb[j] > vv) ? 1u : 0u;
                if (r == kB - 1u) sh_T = vv;
            }
            __syncthreads();
            const unsigned long long T = sh_T;

            // ---- Phase 5: scatter the 64 kept values over the zeros ----
            for (unsigned s = tid; s < cnt; s += THREADS) {
                const unsigned long long cv = cand[s];
                const unsigned bits = (unsigned)(cv >> 13);
                unsigned d = (bits - 0x40000000u) >> 17;
                if (d > 127u) d = 127u;
                if (d > B || (d == B && cv >= T)) {
                    const unsigned col = 8191u - (unsigned)(cv & 8191ull);
                    orow[col] = __uint_as_float(bits);
                }
            }
            return;
        }
        // tc overflow -> fall through to generic fallback
    }

    // ================= Generic fallback (never taken for N(0,1) data) ======
    __shared__ unsigned sh_prefix, sh_kk, sh_tcnt, sh_cut;
    if (tid == 0) { sh_prefix = 0u; sh_kk = KTOP; }

    for (int p = 0; p < 4; ++p) {
        __syncthreads();
        const unsigned prefix = sh_prefix;
        const unsigned kRem   = sh_kk;
        hist[tid] = 0u;
        __syncthreads();
        for (int jj = 0; jj < FVECS; ++jj) {
            const float4 v = in4[tid + THREADS * jj];
            #pragma unroll
            for (int c = 0; c < 4; ++c) {
                const unsigned key = mono(__float_as_uint((&v.x)[c]));
                const bool act = (p == 0) || ((key >> (32 - 8 * p)) == prefix);
                if (act)
                    atomicAdd(&hist[(key >> (24 - 8 * p)) & 0xffu], 1u);
            }
        }
        __syncthreads();
        const unsigned v  = hist[255 - tid];
        unsigned sc = v;
        #pragma unroll
        for (int off = 1; off < 32; off <<= 1) {
            const unsigned y = __shfl_up_sync(0xffffffffu, sc, off);
            if (lane >= off) sc += y;
        }
        if (lane == 31) wsum[wid] = sc;
        __syncthreads();
        unsigned add = 0u;
        #pragma unroll
        for (int w = 0; w < 8; ++w) add += (w < wid) ? wsum[w] : 0u;
        const unsigned incl = sc + add;
        const unsigned excl = incl - v;
        if (excl < kRem && kRem <= incl) {
            sh_prefix = (prefix << 8) | (255u - (unsigned)tid);
            sh_kk     = kRem - excl;
        }
    }
    __syncthreads();
    const unsigned Tk = sh_prefix;
    const unsigned kT = sh_kk;

    unsigned* tcol = (unsigned*)cand;
    if (tid == 0) sh_tcnt = 0u;
    __syncthreads();
    for (int jj = 0; jj < FVECS; ++jj) {
        const float4 v = in4[tid + THREADS * jj];
        #pragma unroll
        for (int c = 0; c < 4; ++c) {
            const unsigned key = mono(__float_as_uint((&v.x)[c]));
            if (key == Tk) {
                const unsigned col = 4u * ((unsigned)tid + THREADS * jj) + (unsigned)c;
                const unsigned pos = atomicAdd(&sh_tcnt, 1u);
                if (pos < 2u * CAP) tcol[pos] = col;
            }
        }
    }
    __syncthreads();
    if (tid == 0) {
        unsigned c = sh_tcnt; if (c > 2u * CAP) c = 2u * CAP;
        unsigned cut = 0xffffffffu;
        for (unsigned s = 0; s < kT; ++s) {
            unsigned mn = 0xffffffffu, mi = 0u;
            for (unsigned i = 0; i < c; ++i)
                if (tcol[i] < mn) { mn = tcol[i]; mi = i; }
            tcol[mi] = 0xffffffffu;
            cut = mn;
        }
        sh_cut = cut;
    }
    __syncthreads();
    const unsigned cut = sh_cut;

    for (int jj = 0; jj < FVECS; ++jj) {
        const float4 v = in4[tid + THREADS * jj];
        float4 o;
        #pragma unroll
        for (int c = 0; c < 4; ++c) {
            const unsigned key = mono(__float_as_uint((&v.x)[c]));
            const unsigned col = 4u * ((unsigned)tid + THREADS * jj) + (unsigned)c;
            const bool keep = (key > Tk) || (key == Tk && col <= cut);
            (&o.x)[c] = keep ? (&v.x)[c] : 0.0f;
        }
        out4[tid + THREADS * jj] = o;
    }
}

extern "C" void kernel_launch(void* const* d_in, const int* in_sizes, int n_in,
                              void* d_out, int out_size) {
    const float* x = (const float*)d_in[0];
    float* out = (float*)d_out;
    const int rows = in_sizes[0] / NCOLS;
    topk_mask_kernel<<<rows, THREADS>>>(x, out, rows);
}